// round 12
// baseline (speedup 1.0000x reference)
#include <cuda_runtime.h>
#include <cuda_bf16.h>
#include <cstdint>

// ---------------- scratch (device globals; no runtime allocation) ----------
// NOTE: these symbols are referenced ONLY inside device code. Passing them as
// kernel arguments from host code binds the HOST shadow variable (ATS makes it
// dereferenceable on GB300, silently reading host zeros) — that was the round
// 8-11 bug.
#define B 16
#define C 512
#define HW 4096              // 64*64
#define PADHW 4356           // 66*66
#define CINF 1040            // padded 1025 -> 1040 (65 chunks of 16)
#define L 256                // patches per image
#define D 8192               // 512*16 patch vector length

__device__ __align__(16) float g_P1[B * C * PADHW];       // reflect-padded z
__device__ __align__(16) float g_P2[B * C * PADHW];       // reflect-padded relu(in(conv1))
__device__ __align__(16) float g_y [B * C * HW];          // raw conv out; later Xp[B][L][D]
__device__ __align__(16) float g_x [B * C * HW];          // residual feature x
__device__ __align__(16) float g_catP[B * CINF * PADHW];  // zero-padded concat input for final conv
__device__ __align__(16) float g_Wt1[9 * 512 * 512];
__device__ __align__(16) float g_Wt2[9 * 512 * 512];
__device__ __align__(16) float g_Wtf[9 * CINF * 512];
__device__ __align__(16) float g_G[B * L * L];
__device__ float g_m[B * HW];
__device__ float g_nonmask[B * L];
__device__ float g_invn[B * L];
__device__ int   g_amax[B * L];

// ---------------- helpers ---------------------------------------------------
__device__ __forceinline__ float blockSum256(float v) {
    __shared__ float red[8];
    #pragma unroll
    for (int off = 16; off > 0; off >>= 1) v += __shfl_xor_sync(0xffffffffu, v, off);
    if ((threadIdx.x & 31) == 0) red[threadIdx.x >> 5] = v;
    __syncthreads();
    float s = 0.f;
    #pragma unroll
    for (int i = 0; i < 8; i++) s += red[i];
    __syncthreads();
    return s;
}

// ---------------- small kernels --------------------------------------------
__global__ void zero_catP_k() {
    size_t i = (size_t)blockIdx.x * 256 + threadIdx.x;
    size_t n4 = (size_t)B * CINF * PADHW / 4;
    if (i < n4) reinterpret_cast<float4*>(g_catP)[i] = make_float4(0.f, 0.f, 0.f, 0.f);
}

// Wt[kk][ci][co] = w[co][ci][kk]; zero rows for ci >= Cin.
// sel: 0 -> g_Wt1 (Cin 512), 1 -> g_Wt2 (512), 2 -> g_Wtf (1025 padded to 1040)
__global__ void wt_k(const float* __restrict__ w, int sel) {
    float* Wt  = (sel == 0) ? g_Wt1 : (sel == 1) ? g_Wt2 : g_Wtf;
    int Cin    = (sel == 2) ? 1025 : 512;
    int CinP   = (sel == 2) ? CINF : 512;
    size_t i = (size_t)blockIdx.x * 256 + threadIdx.x;
    size_t tot = (size_t)9 * CinP * 512;
    if (i >= tot) return;
    int co = (int)(i % 512);
    int t  = (int)(i / 512);
    int ci = t % CinP;
    int kk = t / CinP;
    Wt[i] = (ci < Cin) ? w[((size_t)co * Cin + ci) * 9 + kk] : 0.f;
}

__device__ __forceinline__ int refl(int i) { return i < 0 ? -i : (i > 63 ? 126 - i : i); }

__global__ void pad_reflect_k(const float* __restrict__ src) {   // z -> g_P1
    size_t i = (size_t)blockIdx.x * 256 + threadIdx.x;
    size_t tot = (size_t)B * C * PADHW;
    if (i >= tot) return;
    int xx = (int)(i % 66);
    int t  = (int)(i / 66);
    int yy = t % 66;
    int bc = t / 66;
    g_P1[i] = src[(size_t)bc * HW + refl(yy - 1) * 64 + refl(xx - 1)];
}

// ---------------- conv: 128co x 128px tile, scalar FFMA ---------------------
// psel: 0 -> (g_P1, g_Wt1, Cin 512), 1 -> (g_P2, g_Wt2, 512), 2 -> (g_catP, g_Wtf, 1040)
// extOut: if non-null, write there (final conv); else write g_y.
__global__ __launch_bounds__(256, 2)
void conv3x3_k(int psel, float* extOut, const float* __restrict__ bias) {
    const float* P  = (psel == 0) ? g_P1  : (psel == 1) ? g_P2  : g_catP;
    const float* Wt = (psel == 0) ? g_Wt1 : (psel == 1) ? g_Wt2 : g_Wtf;
    float* out = extOut ? extOut : g_y;
    const int Cin = (psel == 2) ? CINF : 512;

    const int b   = blockIdx.z;
    const int co0 = blockIdx.y * 128;
    const int px0 = blockIdx.x * 128;
    const int y0  = px0 >> 6;           // 2 image rows: y0, y0+1
    const int tid = threadIdx.x;
    const int pp  = tid & 15;           // pixel part (8 px)
    const int cp  = tid >> 4;           // co part (8 co)

    __shared__ __align__(16) float As[16 * 128];   // [k][co]
    __shared__ __align__(16) float Bs[16 * 128];   // [k][px]

    float acc[8][8];
    #pragma unroll
    for (int i = 0; i < 8; i++)
        #pragma unroll
        for (int j = 0; j < 8; j++) acc[i][j] = 0.f;

    const int nch = Cin >> 4;
    for (int kk = 0; kk < 9; kk++) {
        const int ky = kk / 3, kx = kk % 3;
        const float* Wbase = Wt + (size_t)kk * Cin * 512 + co0;
        const float* Pbase = P + (((size_t)b * Cin) * 66 + (y0 + ky)) * 66 + kx;
        for (int ch = 0; ch < nch; ch++) {
            __syncthreads();
            #pragma unroll
            for (int i = 0; i < 8; i++) {            // A: 16ci x 128co, coalesced
                int idx = tid + i * 256;
                int ci = idx >> 7, c = idx & 127;
                As[idx] = Wbase[(size_t)(ch * 16 + ci) * 512 + c];
            }
            #pragma unroll
            for (int i = 0; i < 8; i++) {            // B: 16ci x (2 rows x 64 cols)
                int idx = tid + i * 256;
                int ci = idx >> 7, rem = idx & 127;
                int r = rem >> 6, col = rem & 63;
                Bs[idx] = Pbase[(size_t)(ch * 16 + ci) * PADHW + r * 66 + col];
            }
            __syncthreads();
            #pragma unroll
            for (int k = 0; k < 16; k++) {
                float a[8], bb[8];
                *(float4*)&a[0]  = *(const float4*)&As[k * 128 + cp * 8];
                *(float4*)&a[4]  = *(const float4*)&As[k * 128 + cp * 8 + 4];
                *(float4*)&bb[0] = *(const float4*)&Bs[k * 128 + pp * 8];
                *(float4*)&bb[4] = *(const float4*)&Bs[k * 128 + pp * 8 + 4];
                #pragma unroll
                for (int i = 0; i < 8; i++)
                    #pragma unroll
                    for (int j = 0; j < 8; j++)
                        acc[i][j] = fmaf(a[i], bb[j], acc[i][j]);
            }
        }
    }

    // epilogue
    #pragma unroll
    for (int i = 0; i < 8; i++) {
        int co = co0 + cp * 8 + i;
        float bi = bias ? bias[co] : 0.f;
        size_t base = ((size_t)(b * 512 + co)) * HW + px0 + pp * 8;
        #pragma unroll
        for (int j = 0; j < 8; j++)
            out[base + j] = acc[i][j] + bi;
    }
}

// ---------------- instance-norm finalizers ---------------------------------
__global__ __launch_bounds__(256) void finalize1_k() {   // g_y -> relu(IN) -> pad -> g_P2
    int bc = blockIdx.x, tid = threadIdx.x;
    const float* yp = g_y + (size_t)bc * HW;
    float v[16]; float s = 0.f;
    #pragma unroll
    for (int i = 0; i < 16; i++) { v[i] = yp[tid + i * 256]; s += v[i]; }
    s = blockSum256(s);
    float mean = s * (1.f / 4096.f);
    float s2 = 0.f;
    #pragma unroll
    for (int i = 0; i < 16; i++) { float d = v[i] - mean; s2 += d * d; }
    s2 = blockSum256(s2);
    float rs = rsqrtf(s2 * (1.f / 4096.f) + 1e-5f);
    __shared__ float sm[HW];
    #pragma unroll
    for (int i = 0; i < 16; i++) sm[tid + i * 256] = fmaxf((v[i] - mean) * rs, 0.f);
    __syncthreads();
    float* o = g_P2 + (size_t)bc * PADHW;
    for (int i = tid; i < PADHW; i += 256) {
        int xx = i % 66, yy = i / 66;
        o[i] = sm[refl(yy - 1) * 64 + refl(xx - 1)];
    }
}

__global__ __launch_bounds__(256) void finalize2_k(const float* __restrict__ z) {
    int bc = blockIdx.x, tid = threadIdx.x;
    int b = bc >> 9, c = bc & 511;
    const float* yp = g_y + (size_t)bc * HW;
    const float* zp = z   + (size_t)bc * HW;
    float v[16]; float s = 0.f;
    #pragma unroll
    for (int i = 0; i < 16; i++) { v[i] = yp[tid + i * 256]; s += v[i]; }
    s = blockSum256(s);
    float mean = s * (1.f / 4096.f);
    float s2 = 0.f;
    #pragma unroll
    for (int i = 0; i < 16; i++) { float d = v[i] - mean; s2 += d * d; }
    s2 = blockSum256(s2);
    float rs = rsqrtf(s2 * (1.f / 4096.f) + 1e-5f);
    float* cz = g_catP + ((size_t)(b * CINF + c) * 66) * 66;
    #pragma unroll
    for (int i = 0; i < 16; i++) {
        int p = tid + i * 256;
        float zv = zp[p];
        g_x[(size_t)bc * HW + p] = zv + (v[i] - mean) * rs;
        cz[(p >> 6) * 66 + 67 + (p & 63)] = zv;     // z -> cat ch 0..511
    }
}

// ---------------- mask / attention pipeline ---------------------------------
__global__ void mask_k(const float* __restrict__ mask) {
    int idx = blockIdx.x * 256 + threadIdx.x;
    if (idx >= B * HW) return;
    int b = idx >> 12, p = idx & 4095;
    int y = p >> 6, x = p & 63;
    int r0 = max(4 * y - 2, 0), r1 = min(4 * y + 5, 255);
    int c0 = max(4 * x - 2, 0), c1 = min(4 * x + 5, 255);
    const float* mp = mask + (size_t)b * 65536;
    float v = 0.f;
    for (int rr = r0; rr <= r1 && v == 0.f; rr++)
        for (int cc = c0; cc <= c1; cc++)
            if (mp[rr * 256 + cc] > 0.f) { v = 1.f; break; }
    g_m[idx] = v;
    g_catP[((size_t)(b * CINF + 1024) * 66 + y + 1) * 66 + x + 1] = v;
}

__global__ void nonmask_k() {
    int idx = blockIdx.x * 256 + threadIdx.x;
    if (idx >= B * L) return;
    int b = idx >> 8, q = idx & 255;
    int ph = q >> 4, pw = q & 15;
    const float* mp = g_m + (size_t)b * HW;
    int cnt = 0;
    #pragma unroll
    for (int dy = 0; dy < 4; dy++)
        #pragma unroll
        for (int dx = 0; dx < 4; dx++)
            cnt += (mp[(4 * ph + dy) * 64 + 4 * pw + dx] != 0.f);
    g_nonmask[idx] = (cnt >= 10) ? 1.f : 0.f;
}

__global__ void buildXp_k() {   // Xp lives in g_y
    size_t i = (size_t)blockIdx.x * 256 + threadIdx.x;
    if (i >= (size_t)B * L * D) return;
    int d = (int)(i & 8191);
    int q = (int)((i >> 13) & 255);
    int b = (int)(i >> 21);
    int c = d >> 4, r = d & 15, dy = r >> 2, dx = r & 3;
    int ph = q >> 4, pw = q & 15;
    g_y[i] = g_x[(((size_t)(b * 512 + c) * 64) + 4 * ph + dy) * 64 + 4 * pw + dx];
}

__global__ __launch_bounds__(256) void norms_k() {
    int bq = blockIdx.x;
    const float* p = g_y + (size_t)bq * D;
    float s = 0.f;
    for (int i = threadIdx.x; i < D; i += 256) { float v = p[i]; s += v * v; }
    s = blockSum256(s);
    if (threadIdx.x == 0) g_invn[bq] = 1.f / fmaxf(sqrtf(s), 1e-12f);
}

__global__ __launch_bounds__(256) void corr_k() {
    int b = blockIdx.z, q0 = blockIdx.y * 64, k0 = blockIdx.x * 64;
    int tid = threadIdx.x, tq = tid >> 4, tk = tid & 15;
    __shared__ __align__(16) float Aq[16][68];
    __shared__ __align__(16) float Bk[16][68];
    float acc[4][4] = {};
    const float* Ap = g_y + ((size_t)(b * L + q0)) * D;
    const float* Bp = g_y + ((size_t)(b * L + k0)) * D;
    for (int d0 = 0; d0 < D; d0 += 16) {
        __syncthreads();
        #pragma unroll
        for (int i = 0; i < 4; i++) {
            int idx = tid + i * 256;
            int r = idx >> 4, c = idx & 15;
            Aq[c][r] = Ap[(size_t)r * D + d0 + c];
            Bk[c][r] = Bp[(size_t)r * D + d0 + c];
        }
        __syncthreads();
        #pragma unroll
        for (int d = 0; d < 16; d++) {
            float4 av = *(const float4*)&Aq[d][tq * 4];
            float4 bv = *(const float4*)&Bk[d][tk * 4];
            float a[4] = {av.x, av.y, av.z, av.w};
            float bb[4] = {bv.x, bv.y, bv.z, bv.w};
            #pragma unroll
            for (int i = 0; i < 4; i++)
                #pragma unroll
                for (int j = 0; j < 4; j++) acc[i][j] += a[i] * bb[j];
        }
    }
    #pragma unroll
    for (int i = 0; i < 4; i++)
        #pragma unroll
        for (int j = 0; j < 4; j++)
            g_G[((size_t)b * L + q0 + tq * 4 + i) * L + (k0 + tk * 4 + j)] = acc[i][j];
}

__global__ void argmax_k() {
    int b = blockIdx.x, q = threadIdx.x;
    const float* row = g_G + ((size_t)b * L + q) * L;
    const float* nm  = g_nonmask + b * L;
    const float* iv  = g_invn + b * L;
    float best = -3.4e38f; int bi = 0;
    for (int k = 0; k < L; k++) {
        float v = (nm[k] == 1.f) ? -1e9f : row[k] * iv[k];
        if (v > best) { best = v; bi = k; }
    }
    g_amax[b * L + q] = bi;
}

__global__ __launch_bounds__(256) void compose_k() {
    int bq = blockIdx.x;
    int b = bq >> 8, q = bq & 255;
    int kq = g_amax[bq];
    const float* srcp = g_y + ((size_t)(b * L + kq)) * D;
    int ph = q >> 4, pw = q & 15;
    for (int d = threadIdx.x; d < D; d += 256) {
        int c = d >> 4, r = d & 15, dy = r >> 2, dx = r & 3;
        g_catP[(((size_t)(b * CINF + 512 + c)) * 66 + 1 + 4 * ph + dy) * 66 + 1 + 4 * pw + dx]
            = srcp[d];
    }
}

// ---------------- launch -----------------------------------------------------
extern "C" void kernel_launch(void* const* d_in, const int* in_sizes, int n_in,
                              void* d_out, int out_size) {
    // Resolve inputs BY SIZE (robust to metadata.txt ordering).
    const float *z = 0, *mask = 0, *w1 = 0, *w2 = 0, *wf = 0, *bf = 0;
    int nw = 0, nb = 0;
    for (int i = 0; i < n_in; i++) {
        int s = in_sizes[i];
        const float* p = (const float*)d_in[i];
        if (s == 33554432) z = p;
        else if (s == 1048576) mask = p;
        else if (s == 2359296) { if (nw == 0) w1 = p; else w2 = p; nw++; }
        else if (s == 4723200) wf = p;
        else if (s == 512) { if (nb == 2) bf = p; nb++; }
    }
    float* out = (float*)d_out;

    {   // zero the padded concat buffer (borders + pad channels)
        size_t n4 = (size_t)B * CINF * PADHW / 4;
        zero_catP_k<<<(unsigned)((n4 + 255) / 256), 256>>>();
    }
    {   // weight transforms
        size_t t1 = (size_t)9 * 512 * 512;
        wt_k<<<(unsigned)((t1 + 255) / 256), 256>>>(w1, 0);
        wt_k<<<(unsigned)((t1 + 255) / 256), 256>>>(w2, 1);
        size_t tf = (size_t)9 * CINF * 512;
        wt_k<<<(unsigned)((tf + 255) / 256), 256>>>(wf, 2);
    }
    {   // reflect pad z -> g_P1
        size_t tot = (size_t)B * C * PADHW;
        pad_reflect_k<<<(unsigned)((tot + 255) / 256), 256>>>(z);
    }
    dim3 cgrid(32, 4, 16);
    conv3x3_k<<<cgrid, 256>>>(0, nullptr, nullptr);   // g_P1 * g_Wt1 -> g_y
    finalize1_k<<<B * C, 256>>>();
    conv3x3_k<<<cgrid, 256>>>(1, nullptr, nullptr);   // g_P2 * g_Wt2 -> g_y
    finalize2_k<<<B * C, 256>>>(z);

    mask_k<<<(B * HW + 255) / 256, 256>>>(mask);
    nonmask_k<<<(B * L + 255) / 256, 256>>>();
    {
        size_t tot = (size_t)B * L * D;
        buildXp_k<<<(unsigned)((tot + 255) / 256), 256>>>();
    }
    norms_k<<<B * L, 256>>>();
    corr_k<<<dim3(4, 4, 16), 256>>>();
    argmax_k<<<B, 256>>>();
    compose_k<<<B * L, 256>>>();

    conv3x3_k<<<cgrid, 256>>>(2, out, bf);            // g_catP * g_Wtf -> d_out

    (void)n_in; (void)out_size;
}